// round 1
// baseline (speedup 1.0000x reference)
#include <cuda_runtime.h>
#include <cuda_bf16.h>
#include <cstdint>

// Problem constants
#define BB 16
#define CC 256
#define TT 1024
#define DD 18

// Precomputed tables (device globals: no allocation allowed)
__device__ float g_M[256][9][256];    // [j][t][c]
__device__ float g_effw[256][9];      // per-channel fused 9-tap kernel
__device__ float g_effb[256];         // per-channel fused bias

// ---------------------------------------------------------------------------
// Kernel 1: precompute eff_w/eff_b (block 256) and M (blocks 0..255, one j each)
// ---------------------------------------------------------------------------
__global__ void prep_kernel(const float* __restrict__ w3, const float* __restrict__ b3,
                            const float* __restrict__ w5, const float* __restrict__ b5,
                            const float* __restrict__ w9, const float* __restrict__ b9,
                            const float* __restrict__ rw, const float* __restrict__ rb,
                            const float* __restrict__ og, const float* __restrict__ fw) {
    int c = threadIdx.x;
    if (blockIdx.x == 256) {
        // Fused effective kernel: offsets -4..4 map to index 0..8
        float ew[9];
        #pragma unroll
        for (int i = 0; i < 9; i++) ew[i] = 0.f;
        float eb = rb[c];
        #pragma unroll
        for (int d = 0; d < 6; d++) {            // k=3, pad=1: tap i -> off i-1 -> idx i+3
            float r = rw[c * 18 + d];
            eb += r * b3[c * 6 + d];
            #pragma unroll
            for (int i = 0; i < 3; i++) ew[i + 3] += r * w3[(c * 6 + d) * 3 + i];
        }
        #pragma unroll
        for (int d = 0; d < 6; d++) {            // k=5, pad=2: idx i+2
            float r = rw[c * 18 + 6 + d];
            eb += r * b5[c * 6 + d];
            #pragma unroll
            for (int i = 0; i < 5; i++) ew[i + 2] += r * w5[(c * 6 + d) * 5 + i];
        }
        #pragma unroll
        for (int d = 0; d < 6; d++) {            // k=9, pad=4: idx i
            float r = rw[c * 18 + 12 + d];
            eb += r * b9[c * 6 + d];
            #pragma unroll
            for (int i = 0; i < 9; i++) ew[i] += r * w9[(c * 6 + d) * 9 + i];
        }
        #pragma unroll
        for (int i = 0; i < 9; i++) g_effw[c][i] = ew[i];
        g_effb[c] = eb;
    } else {
        // M[j][t][c] = og[j,c] * sum_d fw[j,c,d] * kp[c,d,t]  (t<9)
        int j = blockIdx.x;
        float s[9];
        #pragma unroll
        for (int t = 0; t < 9; t++) s[t] = 0.f;
        const float* f = fw + ((size_t)j * 256 + c) * 18;
        #pragma unroll
        for (int d = 0; d < 6; d++) {
            float fd = f[d];
            #pragma unroll
            for (int t = 0; t < 3; t++) s[t] += fd * w3[(c * 6 + d) * 3 + t];
        }
        #pragma unroll
        for (int d = 0; d < 6; d++) {
            float fd = f[6 + d];
            #pragma unroll
            for (int t = 0; t < 5; t++) s[t] += fd * w5[(c * 6 + d) * 5 + t];
        }
        #pragma unroll
        for (int d = 0; d < 6; d++) {
            float fd = f[12 + d];
            #pragma unroll
            for (int t = 0; t < 9; t++) s[t] += fd * w9[(c * 6 + d) * 9 + t];
        }
        float g = og[(size_t)j * 256 + c];
        #pragma unroll
        for (int t = 0; t < 9; t++) g_M[j][t][c] = g * s[t];
    }
}

// ---------------------------------------------------------------------------
// Kernel 2: fused drive conv + LIF latency scan + x passthrough copy.
// One warp per (b,c) row. Lane l owns timesteps [32l, 32l+32).
// ---------------------------------------------------------------------------
#define WPB 8
__global__ void __launch_bounds__(256, 4)
lif_kernel(const float* __restrict__ x, const float* __restrict__ lat_scale,
           float* __restrict__ out_x, float* __restrict__ out_lat,
           float* __restrict__ out_act) {
    __shared__ float sx[WPB][TT + 16];
    const int warp = threadIdx.x >> 5, lane = threadIdx.x & 31;
    const int row = blockIdx.x * WPB + warp;           // 0..4095 = b*256+c
    const int c = row & 255;
    const float* xr = x + (size_t)row * TT;
    float* xo = out_x + (size_t)row * TT;
    float* s = sx[warp] + 4;                           // s[t] = x[row][t], halo each side

    #pragma unroll
    for (int i = 0; i < 8; i++) {
        int p = i * 128 + lane * 4;
        float4 v = *(const float4*)(xr + p);
        *(float4*)(s + p) = v;
        *(float4*)(xo + p) = v;                        // fused passthrough copy
    }
    if (lane < 4) { s[lane - 4] = 0.f; s[TT + lane] = 0.f; }
    __syncwarp();

    float ew[9];
    #pragma unroll
    for (int i = 0; i < 9; i++) ew[i] = g_effw[c][i];
    const float eb = g_effb[c];

    const float AL  = (float)0.81873075307798185567;   // exp(-1/5), f32-rounded
    const float OM  = (float)0.18126924692201814433;   // 1 - alpha
    const float A32 = (float)0.00166155727317393354;   // alpha^32

    // drive for this lane's 32 steps
    float dloc[32];
    const int t0 = lane * 32;
    #pragma unroll
    for (int ss = 0; ss < 32; ss++) {
        const float* xp = s + t0 + ss - 4;
        float d = eb;
        #pragma unroll
        for (int i = 0; i < 9; i++) d = fmaf(ew[i], xp[i], d);
        dloc[ss] = d;
    }

    // pass 1: local segment value starting from V=0
    float U = 0.f, A = A32;
    #pragma unroll
    for (int ss = 0; ss < 32; ss++) U = fmaf(AL, U, OM * dloc[ss]);

    // Kogge-Stone inclusive scan over (A, U):  (A1,U1)∘(A2,U2) = (A1*A2, A2*U1+U2)
    #pragma unroll
    for (int off = 1; off < 32; off <<= 1) {
        float Au = __shfl_up_sync(0xffffffffu, A, off);
        float Uu = __shfl_up_sync(0xffffffffu, U, off);
        if (lane >= off) { U = fmaf(A, Uu, U); A *= Au; }
    }
    float Vin = __shfl_up_sync(0xffffffffu, U, 1);
    if (lane == 0) Vin = 0.f;

    // pass 2: exact-order local replay with the true carry; first crossing
    float V = Vin;
    int lat = TT;
    #pragma unroll
    for (int ss = 0; ss < 32; ss++) {
        V = fmaf(AL, V, OM * dloc[ss]);
        if (lat == TT && V >= 0.01f) lat = t0 + ss;
    }
    #pragma unroll
    for (int off = 16; off; off >>= 1) lat = min(lat, __shfl_xor_sync(0xffffffffu, lat, off));

    if (lane == 0) {
        float latf = (float)lat;
        float sc = fmaxf(lat_scale[0], 0.001f);
        out_lat[row] = latf;
        out_act[row] = expf(-latf / sc);
    }
}

// ---------------------------------------------------------------------------
// Kernel 3: recon[b,j,t] = sum_c act[b,c]*M[j,t,c] for t<9; zeros elsewhere.
// One warp per (b,j) row; block = 8 warps sharing act[b,:] in smem.
// ---------------------------------------------------------------------------
__global__ void __launch_bounds__(256, 4)
recon_kernel(const float* __restrict__ act, float* __restrict__ recon) {
    __shared__ float sa[256];
    const int b = blockIdx.y;
    const int tid = threadIdx.x;
    sa[tid] = act[b * 256 + tid];
    __syncthreads();

    const int warp = tid >> 5, lane = tid & 31;
    const int j = blockIdx.x * 8 + warp;

    float sums[9];
    #pragma unroll
    for (int t = 0; t < 9; t++) sums[t] = 0.f;

    #pragma unroll
    for (int k = 0; k < 8; k++) {
        int ci = lane + k * 32;
        float a = sa[ci];
        const float* m = &g_M[j][0][ci];
        #pragma unroll
        for (int t = 0; t < 9; t++) sums[t] = fmaf(a, m[t * 256], sums[t]);
    }
    #pragma unroll
    for (int t = 0; t < 9; t++) {
        #pragma unroll
        for (int off = 16; off; off >>= 1)
            sums[t] += __shfl_xor_sync(0xffffffffu, sums[t], off);
    }

    float* r = recon + ((size_t)b * 256 + j) * TT;
    #pragma unroll
    for (int i = 0; i < 8; i++) {
        int p = i * 128 + lane * 4;
        float4 v = make_float4(0.f, 0.f, 0.f, 0.f);
        if (i == 0) {
            if (lane == 0)      v = make_float4(sums[0], sums[1], sums[2], sums[3]);
            else if (lane == 1) v = make_float4(sums[4], sums[5], sums[6], sums[7]);
            else if (lane == 2) v = make_float4(sums[8], 0.f, 0.f, 0.f);
        }
        *(float4*)(r + p) = v;
    }
}

// ---------------------------------------------------------------------------
extern "C" void kernel_launch(void* const* d_in, const int* in_sizes, int n_in,
                              void* d_out, int out_size) {
    const float* x  = (const float*)d_in[0];
    const float* w3 = (const float*)d_in[1];
    const float* b3 = (const float*)d_in[2];
    const float* w5 = (const float*)d_in[3];
    const float* b5 = (const float*)d_in[4];
    const float* w9 = (const float*)d_in[5];
    const float* b9 = (const float*)d_in[6];
    const float* rw = (const float*)d_in[7];
    const float* rb = (const float*)d_in[8];
    const float* ls = (const float*)d_in[9];
    const float* og = (const float*)d_in[10];
    const float* fw = (const float*)d_in[11];

    float* out      = (float*)d_out;
    float* recon    = out;                         // (B,C,T)  4194304
    float* out_x    = out + 4194304;               // (B,C,T)  4194304
    float* out_lat  = out + 8388608;               // (B,C)       4096
    float* out_act  = out + 8392704;               // (B,C)       4096

    prep_kernel<<<257, 256>>>(w3, b3, w5, b5, w9, b9, rw, rb, og, fw);
    lif_kernel<<<4096 / WPB, 256>>>(x, ls, out_x, out_lat, out_act);
    recon_kernel<<<dim3(32, 16), 256>>>(out_act, recon);
}

// round 2
// speedup vs baseline: 1.9667x; 1.9667x over previous
#include <cuda_runtime.h>
#include <cuda_bf16.h>
#include <cstdint>

#define BB 16
#define CC 256
#define TT 1024

// Precomputed tables (device globals: no allocation allowed)
__device__ float g_M[256][9][256];    // [j][t][c]
__device__ float g_effw[256][9];      // per-channel fused 9-tap kernel
__device__ float g_effb[256];         // per-channel fused bias

// ---------------------------------------------------------------------------
// Kernel 1: blocks 0..255 compute M[j][t][c]; block 256 computes effw/effb.
// Vectorized float2 loads, phased to keep register pressure bounded.
// ---------------------------------------------------------------------------
__global__ void __launch_bounds__(256)
prep_kernel(const float* __restrict__ w3, const float* __restrict__ b3,
            const float* __restrict__ w5, const float* __restrict__ b5,
            const float* __restrict__ w9, const float* __restrict__ b9,
            const float* __restrict__ rw, const float* __restrict__ rb,
            const float* __restrict__ og, const float* __restrict__ fw) {
    const int c = threadIdx.x;
    if (blockIdx.x == 256) {
        // ---- fused effective 9-tap kernel + bias ----
        float rwv[18];
        {
            const float2* p = reinterpret_cast<const float2*>(rw + c * 18);
            #pragma unroll
            for (int i = 0; i < 9; i++) { float2 v = p[i]; rwv[2*i] = v.x; rwv[2*i+1] = v.y; }
        }
        float ew[9];
        #pragma unroll
        for (int i = 0; i < 9; i++) ew[i] = 0.f;
        float eb = rb[c];
        {   // k=3, pad=1 -> taps at idx i+3
            float a[18], bv[6];
            const float2* p = reinterpret_cast<const float2*>(w3 + c * 18);
            #pragma unroll
            for (int i = 0; i < 9; i++) { float2 v = p[i]; a[2*i] = v.x; a[2*i+1] = v.y; }
            const float2* q = reinterpret_cast<const float2*>(b3 + c * 6);
            #pragma unroll
            for (int i = 0; i < 3; i++) { float2 v = q[i]; bv[2*i] = v.x; bv[2*i+1] = v.y; }
            #pragma unroll
            for (int d = 0; d < 6; d++) {
                float r = rwv[d];
                eb = fmaf(r, bv[d], eb);
                #pragma unroll
                for (int i = 0; i < 3; i++) ew[i + 3] = fmaf(r, a[d*3+i], ew[i + 3]);
            }
        }
        {   // k=5, pad=2 -> idx i+2
            float a[30], bv[6];
            const float2* p = reinterpret_cast<const float2*>(w5 + c * 30);
            #pragma unroll
            for (int i = 0; i < 15; i++) { float2 v = p[i]; a[2*i] = v.x; a[2*i+1] = v.y; }
            const float2* q = reinterpret_cast<const float2*>(b5 + c * 6);
            #pragma unroll
            for (int i = 0; i < 3; i++) { float2 v = q[i]; bv[2*i] = v.x; bv[2*i+1] = v.y; }
            #pragma unroll
            for (int d = 0; d < 6; d++) {
                float r = rwv[6 + d];
                eb = fmaf(r, bv[d], eb);
                #pragma unroll
                for (int i = 0; i < 5; i++) ew[i + 2] = fmaf(r, a[d*5+i], ew[i + 2]);
            }
        }
        {   // k=9, pad=4 -> idx i
            float a[54], bv[6];
            const float2* p = reinterpret_cast<const float2*>(w9 + c * 54);
            #pragma unroll
            for (int i = 0; i < 27; i++) { float2 v = p[i]; a[2*i] = v.x; a[2*i+1] = v.y; }
            const float2* q = reinterpret_cast<const float2*>(b9 + c * 6);
            #pragma unroll
            for (int i = 0; i < 3; i++) { float2 v = q[i]; bv[2*i] = v.x; bv[2*i+1] = v.y; }
            #pragma unroll
            for (int d = 0; d < 6; d++) {
                float r = rwv[12 + d];
                eb = fmaf(r, bv[d], eb);
                #pragma unroll
                for (int i = 0; i < 9; i++) ew[i] = fmaf(r, a[d*9+i], ew[i]);
            }
        }
        #pragma unroll
        for (int i = 0; i < 9; i++) g_effw[c][i] = ew[i];
        g_effb[c] = eb;
    } else {
        // ---- M[j][t][c] = og[j,c] * sum_d fw[j,c,d] * kp[c,d,t]  (t<9) ----
        const int j = blockIdx.x;
        float f[18];
        {
            const float2* p = reinterpret_cast<const float2*>(fw + ((size_t)j * 256 + c) * 18);
            #pragma unroll
            for (int i = 0; i < 9; i++) { float2 v = p[i]; f[2*i] = v.x; f[2*i+1] = v.y; }
        }
        float s[9];
        #pragma unroll
        for (int t = 0; t < 9; t++) s[t] = 0.f;
        {
            float a[18];
            const float2* p = reinterpret_cast<const float2*>(w3 + c * 18);
            #pragma unroll
            for (int i = 0; i < 9; i++) { float2 v = p[i]; a[2*i] = v.x; a[2*i+1] = v.y; }
            #pragma unroll
            for (int d = 0; d < 6; d++)
                #pragma unroll
                for (int t = 0; t < 3; t++) s[t] = fmaf(f[d], a[d*3+t], s[t]);
        }
        {
            float a[30];
            const float2* p = reinterpret_cast<const float2*>(w5 + c * 30);
            #pragma unroll
            for (int i = 0; i < 15; i++) { float2 v = p[i]; a[2*i] = v.x; a[2*i+1] = v.y; }
            #pragma unroll
            for (int d = 0; d < 6; d++)
                #pragma unroll
                for (int t = 0; t < 5; t++) s[t] = fmaf(f[6+d], a[d*5+t], s[t]);
        }
        {
            float a[54];
            const float2* p = reinterpret_cast<const float2*>(w9 + c * 54);
            #pragma unroll
            for (int i = 0; i < 27; i++) { float2 v = p[i]; a[2*i] = v.x; a[2*i+1] = v.y; }
            #pragma unroll
            for (int d = 0; d < 6; d++)
                #pragma unroll
                for (int t = 0; t < 9; t++) s[t] = fmaf(f[12+d], a[d*9+t], s[t]);
        }
        const float g = og[(size_t)j * 256 + c];
        #pragma unroll
        for (int t = 0; t < 9; t++) g_M[j][t][c] = g * s[t];
    }
}

// ---------------------------------------------------------------------------
// Kernel 2: fused drive conv + LIF latency scan + x passthrough copy.
// One warp per (b,c) row. Lane l owns timesteps [32l, 32l+32).
// smem layout: lane segment at stride 33 words -> conflict-free LDS/STS.
// ---------------------------------------------------------------------------
#define WPB 8
__global__ void __launch_bounds__(256, 3)
lif_kernel(const float* __restrict__ x, const float* __restrict__ lat_scale,
           float* __restrict__ out_x, float* __restrict__ out_lat,
           float* __restrict__ out_act) {
    __shared__ float sx[WPB][33 * 32];
    const int warp = threadIdx.x >> 5, lane = threadIdx.x & 31;
    const int row = blockIdx.x * WPB + warp;           // b*256+c
    const int c = row & 255;
    const float* xr = x + (size_t)row * TT;
    float* xo = out_x + (size_t)row * TT;
    float* sp = sx[warp];

    // stage: coalesced LDG.128, fused passthrough STG.128, conflict-free STS
    #pragma unroll
    for (int i = 0; i < 8; i++) {
        const int p = i * 128 + lane * 4;
        float4 v = *(const float4*)(xr + p);
        *(float4*)(xo + p) = v;
        const int base = 33 * (p >> 5) + (p & 31);
        sp[base + 0] = v.x; sp[base + 1] = v.y; sp[base + 2] = v.z; sp[base + 3] = v.w;
    }
    __syncwarp();

    float ew[9];
    #pragma unroll
    for (int i = 0; i < 9; i++) ew[i] = g_effw[c][i];
    const float eb = g_effb[c];

    const float AL  = (float)0.81873075307798185567;   // exp(-1/5)
    const float OM  = (float)0.18126924692201814433;   // 1 - alpha
    const float A32 = (float)0.00166155727317393354;   // alpha^32

    const int sb = 33 * lane;
    float dloc[32];

    // chunk 0: outputs 0..7, window t-offsets -4..11
    {
        float w[16];
        #pragma unroll
        for (int q = 0; q < 4; q++)  w[q] = (lane > 0) ? sp[sb - 5 + q] : 0.f;
        #pragma unroll
        for (int q = 4; q < 16; q++) w[q] = sp[sb + q - 4];
        #pragma unroll
        for (int k = 0; k < 8; k++) {
            float d = eb;
            #pragma unroll
            for (int i = 0; i < 9; i++) d = fmaf(ew[i], w[k + i], d);
            dloc[k] = d;
        }
    }
    // chunk 1: outputs 8..15, offsets 4..19
    {
        float w[16];
        #pragma unroll
        for (int q = 0; q < 16; q++) w[q] = sp[sb + 4 + q];
        #pragma unroll
        for (int k = 0; k < 8; k++) {
            float d = eb;
            #pragma unroll
            for (int i = 0; i < 9; i++) d = fmaf(ew[i], w[k + i], d);
            dloc[8 + k] = d;
        }
    }
    // chunk 2: outputs 16..23, offsets 12..27
    {
        float w[16];
        #pragma unroll
        for (int q = 0; q < 16; q++) w[q] = sp[sb + 12 + q];
        #pragma unroll
        for (int k = 0; k < 8; k++) {
            float d = eb;
            #pragma unroll
            for (int i = 0; i < 9; i++) d = fmaf(ew[i], w[k + i], d);
            dloc[16 + k] = d;
        }
    }
    // chunk 3: outputs 24..31, offsets 20..35 (cross into lane+1 at offset 32)
    {
        float w[16];
        #pragma unroll
        for (int q = 0; q < 12; q++)  w[q] = sp[sb + 20 + q];
        #pragma unroll
        for (int q = 12; q < 16; q++) w[q] = (lane < 31) ? sp[sb + 21 + q] : 0.f;
        #pragma unroll
        for (int k = 0; k < 8; k++) {
            float d = eb;
            #pragma unroll
            for (int i = 0; i < 9; i++) d = fmaf(ew[i], w[k + i], d);
            dloc[24 + k] = d;
        }
    }

    // pass 1: local segment value starting from V=0
    float U = 0.f, A = A32;
    #pragma unroll
    for (int ss = 0; ss < 32; ss++) U = fmaf(AL, U, OM * dloc[ss]);

    // Kogge-Stone inclusive scan over (A,U): (A1,U1)∘(A2,U2) = (A1*A2, A2*U1+U2)
    #pragma unroll
    for (int off = 1; off < 32; off <<= 1) {
        float Au = __shfl_up_sync(0xffffffffu, A, off);
        float Uu = __shfl_up_sync(0xffffffffu, U, off);
        if (lane >= off) { U = fmaf(A, Uu, U); A *= Au; }
    }
    float Vin = __shfl_up_sync(0xffffffffu, U, 1);
    if (lane == 0) Vin = 0.f;

    // pass 2: exact-order replay with true carry; first crossing
    float V = Vin;
    int lat = TT;
    const int t0 = lane * 32;
    #pragma unroll
    for (int ss = 0; ss < 32; ss++) {
        V = fmaf(AL, V, OM * dloc[ss]);
        if (lat == TT && V >= 0.01f) lat = t0 + ss;
    }
    #pragma unroll
    for (int off = 16; off; off >>= 1) lat = min(lat, __shfl_xor_sync(0xffffffffu, lat, off));

    if (lane == 0) {
        float latf = (float)lat;
        float sc = fmaxf(lat_scale[0], 0.001f);
        out_lat[row] = latf;
        out_act[row] = expf(-latf / sc);
    }
}

// ---------------------------------------------------------------------------
// Kernel 3: recon[b,j,t] = sum_c act[b,c]*M[j,t,c] for t<9; zeros elsewhere.
// ---------------------------------------------------------------------------
__global__ void __launch_bounds__(256, 4)
recon_kernel(const float* __restrict__ act, float* __restrict__ recon) {
    __shared__ float sa[256];
    const int b = blockIdx.y;
    const int tid = threadIdx.x;
    sa[tid] = act[b * 256 + tid];
    __syncthreads();

    const int warp = tid >> 5, lane = tid & 31;
    const int j = blockIdx.x * 8 + warp;

    float sums[9];
    #pragma unroll
    for (int t = 0; t < 9; t++) sums[t] = 0.f;

    #pragma unroll
    for (int k = 0; k < 8; k++) {
        int ci = lane + k * 32;
        float a = sa[ci];
        const float* m = &g_M[j][0][ci];
        #pragma unroll
        for (int t = 0; t < 9; t++) sums[t] = fmaf(a, m[t * 256], sums[t]);
    }
    #pragma unroll
    for (int t = 0; t < 9; t++) {
        #pragma unroll
        for (int off = 16; off; off >>= 1)
            sums[t] += __shfl_xor_sync(0xffffffffu, sums[t], off);
    }

    float* r = recon + ((size_t)b * 256 + j) * TT;
    #pragma unroll
    for (int i = 0; i < 8; i++) {
        int p = i * 128 + lane * 4;
        float4 v = make_float4(0.f, 0.f, 0.f, 0.f);
        if (i == 0) {
            if (lane == 0)      v = make_float4(sums[0], sums[1], sums[2], sums[3]);
            else if (lane == 1) v = make_float4(sums[4], sums[5], sums[6], sums[7]);
            else if (lane == 2) v = make_float4(sums[8], 0.f, 0.f, 0.f);
        }
        *(float4*)(r + p) = v;
    }
}

// ---------------------------------------------------------------------------
extern "C" void kernel_launch(void* const* d_in, const int* in_sizes, int n_in,
                              void* d_out, int out_size) {
    const float* x  = (const float*)d_in[0];
    const float* w3 = (const float*)d_in[1];
    const float* b3 = (const float*)d_in[2];
    const float* w5 = (const float*)d_in[3];
    const float* b5 = (const float*)d_in[4];
    const float* w9 = (const float*)d_in[5];
    const float* b9 = (const float*)d_in[6];
    const float* rw = (const float*)d_in[7];
    const float* rb = (const float*)d_in[8];
    const float* ls = (const float*)d_in[9];
    const float* og = (const float*)d_in[10];
    const float* fw = (const float*)d_in[11];

    float* out      = (float*)d_out;
    float* recon    = out;                         // (B,C,T)  4194304
    float* out_x    = out + 4194304;               // (B,C,T)  4194304
    float* out_lat  = out + 8388608;               // (B,C)       4096
    float* out_act  = out + 8392704;               // (B,C)       4096

    prep_kernel<<<257, 256>>>(w3, b3, w5, b5, w9, b9, rw, rb, og, fw);
    lif_kernel<<<4096 / WPB, 256>>>(x, ls, out_x, out_lat, out_act);
    recon_kernel<<<dim3(32, 16), 256>>>(out_act, recon);
}

// round 3
// speedup vs baseline: 2.1618x; 1.0992x over previous
#include <cuda_runtime.h>
#include <cuda_bf16.h>
#include <cstdint>

#define BB 16
#define CC 256
#define TT 1024

// Precomputed table (device global: no allocation allowed)
__device__ float g_M[256][9][256];    // [j][t][c]

// ---------------------------------------------------------------------------
// Fused kernel: blocks [0,512) run LIF (8 rows each, effw computed in-warp);
// blocks [512,1024) compute M[j][t][c-half] (j = (bid-512)>>1, half = bid&1).
// These two halves are independent -> prep latency hides under lif bandwidth.
// ---------------------------------------------------------------------------
#define LIF_BLOCKS 512
__global__ void __launch_bounds__(256)
fused_kernel(const float* __restrict__ x,
             const float* __restrict__ w3, const float* __restrict__ b3,
             const float* __restrict__ w5, const float* __restrict__ b5,
             const float* __restrict__ w9, const float* __restrict__ b9,
             const float* __restrict__ rw, const float* __restrict__ rb,
             const float* __restrict__ ls,
             const float* __restrict__ og, const float* __restrict__ fw,
             float* __restrict__ out_x, float* __restrict__ out_lat,
             float* __restrict__ out_act) {
    __shared__ float smem[8 * 33 * 32];                 // 33792 B, reused by both roles

    if (blockIdx.x < LIF_BLOCKS) {
        // =================== LIF role ===================
        const int warp = threadIdx.x >> 5, lane = threadIdx.x & 31;
        const int row = blockIdx.x * 8 + warp;          // b*256+c
        const int c = row & 255;
        const float* xr = x + (size_t)row * TT;
        float* xo = out_x + (size_t)row * TT;
        float* sp = smem + warp * (33 * 32);

        // stage x: coalesced LDG.128, fused passthrough STG.128, conflict-free STS
        #pragma unroll
        for (int i = 0; i < 8; i++) {
            const int p = i * 128 + lane * 4;
            float4 v = *(const float4*)(xr + p);
            *(float4*)(xo + p) = v;
            const int base = 33 * (p >> 5) + (p & 31);
            sp[base + 0] = v.x; sp[base + 1] = v.y; sp[base + 2] = v.z; sp[base + 3] = v.w;
        }

        // ---- per-warp effective 9-tap kernel: lane d in [0,18) handles one dendrite ----
        float ew[9];
        #pragma unroll
        for (int i = 0; i < 9; i++) ew[i] = 0.f;
        float eb = 0.f;
        {
            const int d = lane;
            if (d < 6) {
                float r = rw[c * 18 + d];
                eb = r * b3[c * 6 + d];
                #pragma unroll
                for (int i = 0; i < 3; i++) ew[i + 3] = r * w3[(c * 6 + d) * 3 + i];
            } else if (d < 12) {
                int dd = d - 6;
                float r = rw[c * 18 + d];
                eb = r * b5[c * 6 + dd];
                #pragma unroll
                for (int i = 0; i < 5; i++) ew[i + 2] = r * w5[(c * 6 + dd) * 5 + i];
            } else if (d < 18) {
                int dd = d - 12;
                float r = rw[c * 18 + d];
                eb = r * b9[c * 6 + dd];
                #pragma unroll
                for (int i = 0; i < 9; i++) ew[i] = r * w9[(c * 6 + dd) * 9 + i];
            } else if (d == 31) {
                eb = rb[c];
            }
        }
        // butterfly reduce -> every lane gets full ew/eb
        #pragma unroll
        for (int off = 16; off; off >>= 1) {
            #pragma unroll
            for (int i = 0; i < 9; i++) ew[i] += __shfl_xor_sync(0xffffffffu, ew[i], off);
            eb += __shfl_xor_sync(0xffffffffu, eb, off);
        }
        __syncwarp();

        const float AL  = (float)0.81873075307798185567;   // exp(-1/5)
        const float OM  = (float)0.18126924692201814433;   // 1 - alpha
        const float A32 = (float)0.00166155727317393354;   // alpha^32

        const int sb = 33 * lane;
        float dloc[32];

        {   // outputs 0..7, t-offsets -4..11
            float w[16];
            #pragma unroll
            for (int q = 0; q < 4; q++)  w[q] = (lane > 0) ? sp[sb - 5 + q] : 0.f;
            #pragma unroll
            for (int q = 4; q < 16; q++) w[q] = sp[sb + q - 4];
            #pragma unroll
            for (int k = 0; k < 8; k++) {
                float d = eb;
                #pragma unroll
                for (int i = 0; i < 9; i++) d = fmaf(ew[i], w[k + i], d);
                dloc[k] = d;
            }
        }
        {   // outputs 8..15
            float w[16];
            #pragma unroll
            for (int q = 0; q < 16; q++) w[q] = sp[sb + 4 + q];
            #pragma unroll
            for (int k = 0; k < 8; k++) {
                float d = eb;
                #pragma unroll
                for (int i = 0; i < 9; i++) d = fmaf(ew[i], w[k + i], d);
                dloc[8 + k] = d;
            }
        }
        {   // outputs 16..23
            float w[16];
            #pragma unroll
            for (int q = 0; q < 16; q++) w[q] = sp[sb + 12 + q];
            #pragma unroll
            for (int k = 0; k < 8; k++) {
                float d = eb;
                #pragma unroll
                for (int i = 0; i < 9; i++) d = fmaf(ew[i], w[k + i], d);
                dloc[16 + k] = d;
            }
        }
        {   // outputs 24..31 (cross into lane+1 at offset 32)
            float w[16];
            #pragma unroll
            for (int q = 0; q < 12; q++)  w[q] = sp[sb + 20 + q];
            #pragma unroll
            for (int q = 12; q < 16; q++) w[q] = (lane < 31) ? sp[sb + 21 + q] : 0.f;
            #pragma unroll
            for (int k = 0; k < 8; k++) {
                float d = eb;
                #pragma unroll
                for (int i = 0; i < 9; i++) d = fmaf(ew[i], w[k + i], d);
                dloc[24 + k] = d;
            }
        }

        // pass 1: local segment value from V=0
        float U = 0.f, A = A32;
        #pragma unroll
        for (int ss = 0; ss < 32; ss++) U = fmaf(AL, U, OM * dloc[ss]);

        // Kogge-Stone scan over (A,U): (A1,U1)∘(A2,U2) = (A1*A2, A2*U1+U2)
        #pragma unroll
        for (int off = 1; off < 32; off <<= 1) {
            float Au = __shfl_up_sync(0xffffffffu, A, off);
            float Uu = __shfl_up_sync(0xffffffffu, U, off);
            if (lane >= off) { U = fmaf(A, Uu, U); A *= Au; }
        }
        float Vin = __shfl_up_sync(0xffffffffu, U, 1);
        if (lane == 0) Vin = 0.f;

        // pass 2: exact-order replay, first crossing
        float V = Vin;
        int lat = TT;
        const int t0 = lane * 32;
        #pragma unroll
        for (int ss = 0; ss < 32; ss++) {
            V = fmaf(AL, V, OM * dloc[ss]);
            if (lat == TT && V >= 0.01f) lat = t0 + ss;
        }
        #pragma unroll
        for (int off = 16; off; off >>= 1) lat = min(lat, __shfl_xor_sync(0xffffffffu, lat, off));

        if (lane == 0) {
            float latf = (float)lat;
            float sc = fmaxf(ls[0], 0.001f);
            out_lat[row] = latf;
            out_act[row] = expf(-latf / sc);
        }
    } else {
        // =================== M-prep role ===================
        // m = bid-512; j = m>>1; 128 channels per block; two thread-halves:
        //   part A (tid<128): w3+w5 contributions (t<5) -> smem
        //   part B (tid>=128): w9 contributions (t<9), combine, scale by og, store
        const int m = blockIdx.x - LIF_BLOCKS;
        const int j = m >> 1;
        const int cbase = (m & 1) * 128;
        const int ci = threadIdx.x & 127;
        const int c = cbase + ci;
        float* sA = smem;                               // [128][6] used

        if (threadIdx.x < 128) {
            float f[12];
            {
                const float2* p = reinterpret_cast<const float2*>(fw + ((size_t)j * 256 + c) * 18);
                #pragma unroll
                for (int i = 0; i < 6; i++) { float2 v = p[i]; f[2*i] = v.x; f[2*i+1] = v.y; }
            }
            float s[5];
            #pragma unroll
            for (int t = 0; t < 5; t++) s[t] = 0.f;
            {
                float a[18];
                const float2* p = reinterpret_cast<const float2*>(w3 + c * 18);
                #pragma unroll
                for (int i = 0; i < 9; i++) { float2 v = p[i]; a[2*i] = v.x; a[2*i+1] = v.y; }
                #pragma unroll
                for (int d = 0; d < 6; d++)
                    #pragma unroll
                    for (int t = 0; t < 3; t++) s[t] = fmaf(f[d], a[d*3+t], s[t]);
            }
            {
                float a[30];
                const float2* p = reinterpret_cast<const float2*>(w5 + c * 30);
                #pragma unroll
                for (int i = 0; i < 15; i++) { float2 v = p[i]; a[2*i] = v.x; a[2*i+1] = v.y; }
                #pragma unroll
                for (int d = 0; d < 6; d++)
                    #pragma unroll
                    for (int t = 0; t < 5; t++) s[t] = fmaf(f[6+d], a[d*5+t], s[t]);
            }
            #pragma unroll
            for (int t = 0; t < 5; t++) sA[ci * 6 + t] = s[t];
            __syncthreads();
        } else {
            float f[6];
            {
                const float2* p = reinterpret_cast<const float2*>(fw + ((size_t)j * 256 + c) * 18 + 12);
                #pragma unroll
                for (int i = 0; i < 3; i++) { float2 v = p[i]; f[2*i] = v.x; f[2*i+1] = v.y; }
            }
            const float g = og[(size_t)j * 256 + c];
            float s[9];
            #pragma unroll
            for (int t = 0; t < 9; t++) s[t] = 0.f;
            {
                float a[54];
                const float2* p = reinterpret_cast<const float2*>(w9 + c * 54);
                #pragma unroll
                for (int i = 0; i < 27; i++) { float2 v = p[i]; a[2*i] = v.x; a[2*i+1] = v.y; }
                #pragma unroll
                for (int d = 0; d < 6; d++)
                    #pragma unroll
                    for (int t = 0; t < 9; t++) s[t] = fmaf(f[d], a[d*9+t], s[t]);
            }
            __syncthreads();
            #pragma unroll
            for (int t = 0; t < 5; t++) s[t] += sA[ci * 6 + t];
            #pragma unroll
            for (int t = 0; t < 9; t++) g_M[j][t][c] = g * s[t];
        }
    }
}

// ---------------------------------------------------------------------------
// recon: warp handles one j and 4 batches; M[j] held in registers (72/lane).
// recon[b,j,t<9] = sum_c act[b,c]*M[j,t,c]; t>=9 zero-filled.
// grid 256 blocks x 128 threads: bid -> (jg = bid&63, bg = bid>>6).
// ---------------------------------------------------------------------------
__global__ void __launch_bounds__(128)
recon_kernel(const float* __restrict__ act, float* __restrict__ recon) {
    const int warp = threadIdx.x >> 5, lane = threadIdx.x & 31;
    const int j = (blockIdx.x & 63) * 4 + warp;
    const int b0 = (blockIdx.x >> 6) * 4;

    // load M[j][t][lane+32k] into regs
    float mreg[72];                                     // [t*8+k]
    #pragma unroll
    for (int t = 0; t < 9; t++)
        #pragma unroll
        for (int k = 0; k < 8; k++)
            mreg[t * 8 + k] = g_M[j][t][lane + 32 * k];

    #pragma unroll
    for (int bi = 0; bi < 4; bi++) {
        const int b = b0 + bi;
        float sums[9];
        #pragma unroll
        for (int t = 0; t < 9; t++) sums[t] = 0.f;
        #pragma unroll
        for (int k = 0; k < 8; k++) {
            float a = act[b * 256 + lane + 32 * k];
            #pragma unroll
            for (int t = 0; t < 9; t++) sums[t] = fmaf(a, mreg[t * 8 + k], sums[t]);
        }
        #pragma unroll
        for (int t = 0; t < 9; t++) {
            #pragma unroll
            for (int off = 16; off; off >>= 1)
                sums[t] += __shfl_xor_sync(0xffffffffu, sums[t], off);
        }

        float* r = recon + ((size_t)b * 256 + j) * TT;
        #pragma unroll
        for (int i = 0; i < 8; i++) {
            int p = i * 128 + lane * 4;
            float4 v = make_float4(0.f, 0.f, 0.f, 0.f);
            if (i == 0) {
                if (lane == 0)      v = make_float4(sums[0], sums[1], sums[2], sums[3]);
                else if (lane == 1) v = make_float4(sums[4], sums[5], sums[6], sums[7]);
                else if (lane == 2) v = make_float4(sums[8], 0.f, 0.f, 0.f);
            }
            *(float4*)(r + p) = v;
        }
    }
}

// ---------------------------------------------------------------------------
extern "C" void kernel_launch(void* const* d_in, const int* in_sizes, int n_in,
                              void* d_out, int out_size) {
    const float* x  = (const float*)d_in[0];
    const float* w3 = (const float*)d_in[1];
    const float* b3 = (const float*)d_in[2];
    const float* w5 = (const float*)d_in[3];
    const float* b5 = (const float*)d_in[4];
    const float* w9 = (const float*)d_in[5];
    const float* b9 = (const float*)d_in[6];
    const float* rw = (const float*)d_in[7];
    const float* rb = (const float*)d_in[8];
    const float* ls = (const float*)d_in[9];
    const float* og = (const float*)d_in[10];
    const float* fw = (const float*)d_in[11];

    float* out      = (float*)d_out;
    float* recon    = out;                         // (B,C,T)  4194304
    float* out_x    = out + 4194304;               // (B,C,T)  4194304
    float* out_lat  = out + 8388608;               // (B,C)       4096
    float* out_act  = out + 8392704;               // (B,C)       4096

    fused_kernel<<<1024, 256>>>(x, w3, b3, w5, b5, w9, b9, rw, rb, ls, og, fw,
                                out_x, out_lat, out_act);
    recon_kernel<<<256, 128>>>(out_act, recon);
}